// round 11
// baseline (speedup 1.0000x reference)
#include <cuda_runtime.h>
#include <cstdint>

// out[mu[k], e] += X1[m1[k], e] * X2[m2[k], e] * mult[k]
// M=9, K~100 runtime terms (mu pre-sorted), ND = N*D = 2^20, fp32.
//
// R11: persistent double-buffered kernel. 444 CTAs (3/SM), 128 threads, one
// float4 column per thread over 512-float tiles. Two 36.9KB smem buffers:
// compute tile t from one while TMA fills the other with tile t+1. Tiles
// claimed via global atomic ticket (reset by a tiny prefix kernel). Program
// (flat, padded, {off1|off2<<16, mult}) built once per CTA. Inner loop =
// R10's: LDS.128 pairs, packed f32x2 math, unroll-2, prog prefetch.

#define M_CH    9
#define TILE    512                    // floats per channel per tile
#define TILE_B  (TILE * 4)             // 2048 B per channel tile
#define BUF_B   (2 * M_CH * TILE_B)    // 36864 B per buffer (X1+X2, 18 ch)
#define THREADS 128
#define NCTAS   444                    // 3 per SM x 148
#define MAXK    128
#define PROGMAX 144

__device__ unsigned int g_ticket;

__global__ void reset_kernel(unsigned int v) { g_ticket = v; }

struct Smem {
    float4 buf[2][2 * M_CH * (TILE / 4)];  // 2 x 36864 B
    int2   prog[PROGMAX];
    int    rawmu[MAXK];
    int    seg[16];
    int    pseg[16];
    unsigned long long mbar[2];
    int    next_tk;
};

__device__ __forceinline__ void mbar_wait(uint32_t addr, int parity)
{
    asm volatile(
        "{\n\t.reg .pred P;\n\t"
        "W_%=:\n\t"
        "mbarrier.try_wait.parity.acquire.cta.shared::cta.b64 P, [%0], %1, 0x989680;\n\t"
        "@P bra.uni D_%=;\n\t"
        "bra.uni W_%=;\n\t"
        "D_%=:\n\t}"
        :: "r"(addr), "r"(parity) : "memory");
}

__device__ __forceinline__ void issue_tile_tma(
    uint32_t dst, const float* X1, const float* X2,
    int tile, int nd4, uint32_t mbar_addr)
{
    asm volatile("mbarrier.arrive.expect_tx.shared.b64 _, [%0], %1;"
                 :: "r"(mbar_addr), "r"((uint32_t)BUF_B) : "memory");
    const char* src1 = (const char*)(X1 + (size_t)tile * TILE);
    const char* src2 = (const char*)(X2 + (size_t)tile * TILE);
    const size_t chanstride = (size_t)nd4 * 16;
#pragma unroll
    for (int m = 0; m < M_CH; m++) {
        asm volatile(
            "cp.async.bulk.shared::cta.global.mbarrier::complete_tx::bytes "
            "[%0], [%1], %2, [%3];"
            :: "r"(dst + m * TILE_B), "l"(src1 + m * chanstride),
               "r"((uint32_t)TILE_B), "r"(mbar_addr) : "memory");
        asm volatile(
            "cp.async.bulk.shared::cta.global.mbarrier::complete_tx::bytes "
            "[%0], [%1], %2, [%3];"
            :: "r"(dst + (M_CH + m) * TILE_B), "l"(src2 + m * chanstride),
               "r"((uint32_t)TILE_B), "r"(mbar_addr) : "memory");
    }
}

__global__ void __launch_bounds__(THREADS, 3)
fused_kernel(const float* __restrict__ X1, const float* __restrict__ X2,
             const int* __restrict__ m1, const int* __restrict__ m2,
             const int* __restrict__ mu, const float* __restrict__ mult,
             float* __restrict__ out, int nd4, int K, int ntiles)
{
    extern __shared__ char smem_raw[];
    Smem* s = (Smem*)smem_raw;
    const int t = threadIdx.x;
    const int bid = blockIdx.x;

    const uint32_t mb0  = (uint32_t)__cvta_generic_to_shared(&s->mbar[0]);
    const uint32_t mb1  = (uint32_t)__cvta_generic_to_shared(&s->mbar[1]);
    const uint32_t buf0 = (uint32_t)__cvta_generic_to_shared(&s->buf[0][0]);
    const uint32_t buf1 = (uint32_t)__cvta_generic_to_shared(&s->buf[1][0]);

    // ---- t0: init mbars, fire both initial TMAs immediately ---------------
    int tile      = bid;                 // goes into buf0
    int tile_next = bid + NCTAS;         // goes into buf1
    if (t == 0) {
        asm volatile("mbarrier.init.shared.b64 [%0], %1;"
                     :: "r"(mb0), "r"(1) : "memory");
        asm volatile("mbarrier.init.shared.b64 [%0], %1;"
                     :: "r"(mb1), "r"(1) : "memory");
        asm volatile("fence.proxy.async.shared::cta;" ::: "memory");
        if (tile < ntiles)
            issue_tile_tma(buf0, X1, X2, tile, nd4, mb0);
        if (tile_next < ntiles)
            issue_tile_tma(buf1, X1, X2, tile_next, nd4, mb1);
    }

    // ---- setup: term data + program (once per persistent CTA) -------------
    int myMu = 0, myPack = 0, myMult = 0;
    const bool has_term = (t < K);
    if (has_term) {
        myMu   = mu[t];
        myPack = (m1[t] * TILE_B) | ((m2[t] * TILE_B) << 16);
        myMult = __float_as_int(mult[t]);
        s->rawmu[t] = myMu;
    }
    __syncthreads();                     // rawmu + mbar init visible

    if (t < 16) {                        // warp 0: seg + pseg + pads
        int segv = 0;
        if (t <= M_CH) {
            for (int j = 0; j < K; j++) segv += (s->rawmu[j] < t);
            s->seg[t] = segv;
        }
        const unsigned msk = 0xFFFFu;
        int segn = __shfl_down_sync(msk, segv, 1);
        int len  = segn - segv;          // valid lanes 0..8
        int plen = (len + 1) & ~1;
        int x = plen;
#pragma unroll
        for (int d = 1; d < 16; d <<= 1) {
            int y = __shfl_up_sync(msk, x, d);
            if (t >= d) x += y;
        }
        int psegv = x - plen;            // exclusive scan
        if (t <= 8) {
            s->pseg[t] = psegv;
            if (len & 1)
                s->prog[psegv + len] = make_int2(0, 0);   // mult=0 dummy
            if (t == 8) s->pseg[9] = psegv + plen;
        }
    }
    __syncthreads();

    if (has_term) {
        const int pos = s->pseg[myMu] + (t - s->seg[myMu]);
        s->prog[pos] = make_int2(myPack, myMult);
    }
    __syncthreads();

    // ---- persistent pipelined tile loop ------------------------------------
    float4* __restrict__ out4 = (float4*)out;
    int cur = 0;
    int ph0 = 0, ph1 = 0;

    while (tile < ntiles) {
        // grab a future ticket early; latency hides under compute
        if (t == 0) {
            unsigned tk = atomicAdd(&g_ticket, 1u);
            s->next_tk = (int)tk;
        }

        // wait for current buffer's data
        if (cur == 0) { mbar_wait(mb0, ph0); ph0 ^= 1; }
        else          { mbar_wait(mb1, ph1); ph1 ^= 1; }

        // ---- compute tile from buf[cur] (R10 inner loop) -------------------
        const uint32_t colb  = (cur ? buf1 : buf0) + t * 16;
        const uint32_t colb2 = colb + M_CH * TILE_B;
        const int tbase4 = tile * (TILE / 4);
        int kptr = 0;

#pragma unroll
        for (int m = 0; m < M_CH; m++) {
            unsigned long long aL0 = 0ull, aH0 = 0ull;
            unsigned long long aL1 = 0ull, aH1 = 0ull;
            const int k1 = s->pseg[m + 1];
            int k = kptr;
            int4 pr = *(const int4*)&s->prog[k];
            for (; k < k1; k += 2) {
                const int4 curp = pr;
                pr = *(const int4*)&s->prog[k + 2];        // padded: safe
                {
                    unsigned long long a0, a1, b0, b1, c2;
                    asm("ld.shared.v2.u64 {%0, %1}, [%2];"
                        : "=l"(a0), "=l"(a1) : "r"(colb + (curp.x & 0xFFFF)));
                    asm("ld.shared.v2.u64 {%0, %1}, [%2];"
                        : "=l"(b0), "=l"(b1) : "r"(colb2 + ((unsigned)curp.x >> 16)));
                    asm("mov.b64 %0, {%1, %1};" : "=l"(c2) : "r"(curp.y));
                    asm("mul.rn.f32x2 %0, %1, %2;" : "=l"(b0) : "l"(c2), "l"(b0));
                    asm("mul.rn.f32x2 %0, %1, %2;" : "=l"(b1) : "l"(c2), "l"(b1));
                    asm("fma.rn.f32x2 %0, %1, %2, %3;"
                        : "=l"(aL0) : "l"(a0), "l"(b0), "l"(aL0));
                    asm("fma.rn.f32x2 %0, %1, %2, %3;"
                        : "=l"(aH0) : "l"(a1), "l"(b1), "l"(aH0));
                }
                {
                    unsigned long long a0, a1, b0, b1, c2;
                    asm("ld.shared.v2.u64 {%0, %1}, [%2];"
                        : "=l"(a0), "=l"(a1) : "r"(colb + (curp.z & 0xFFFF)));
                    asm("ld.shared.v2.u64 {%0, %1}, [%2];"
                        : "=l"(b0), "=l"(b1) : "r"(colb2 + ((unsigned)curp.z >> 16)));
                    asm("mov.b64 %0, {%1, %1};" : "=l"(c2) : "r"(curp.w));
                    asm("mul.rn.f32x2 %0, %1, %2;" : "=l"(b0) : "l"(c2), "l"(b0));
                    asm("mul.rn.f32x2 %0, %1, %2;" : "=l"(b1) : "l"(c2), "l"(b1));
                    asm("fma.rn.f32x2 %0, %1, %2, %3;"
                        : "=l"(aL1) : "l"(a0), "l"(b0), "l"(aL1));
                    asm("fma.rn.f32x2 %0, %1, %2, %3;"
                        : "=l"(aH1) : "l"(a1), "l"(b1), "l"(aH1));
                }
            }
            kptr = k1;
            ulonglong2 acc;
            asm("add.rn.f32x2 %0, %1, %2;" : "=l"(acc.x) : "l"(aL0), "l"(aL1));
            asm("add.rn.f32x2 %0, %1, %2;" : "=l"(acc.y) : "l"(aH0), "l"(aH1));
            *(ulonglong2*)&out4[(size_t)m * nd4 + tbase4 + t] = acc;
        }

        __syncthreads();                 // all reads of buf[cur] done; next_tk visible
        const int tk = s->next_tk;
        if (t == 0 && tk < ntiles)
            issue_tile_tma(cur ? buf1 : buf0, X1, X2, tk, nd4, cur ? mb1 : mb0);

        tile = tile_next;
        tile_next = tk;
        cur ^= 1;
    }
}

extern "C" void kernel_launch(void* const* d_in, const int* in_sizes, int n_in,
                              void* d_out, int out_size)
{
    const float* X1   = (const float*)d_in[0];
    const float* X2   = (const float*)d_in[1];
    const int*   m1   = (const int*)d_in[2];
    const int*   m2   = (const int*)d_in[3];
    const int*   mu   = (const int*)d_in[4];
    const float* mult = (const float*)d_in[5];
    float*       out  = (float*)d_out;

    const int K      = in_sizes[2];
    const int ND     = in_sizes[0] / M_CH;   // N*D
    const int nd4    = ND / 4;
    const int ntiles = ND / TILE;

    reset_kernel<<<1, 1>>>(2u * NCTAS);      // tickets for tiles beyond the
                                             // 2*NCTAS pre-assigned ones
    const int smem = (int)sizeof(Smem);
    cudaFuncSetAttribute(fused_kernel,
                         cudaFuncAttributeMaxDynamicSharedMemorySize, smem);
    fused_kernel<<<NCTAS, THREADS, smem>>>(X1, X2, m1, m2, mu, mult,
                                           out, nd4, K, ntiles);
}

// round 12
// speedup vs baseline: 1.0074x; 1.0074x over previous
#include <cuda_runtime.h>
#include <cstdint>

// out[mu[k], e] += X1[m1[k], e] * X2[m2[k], e] * mult[k]
// M=9, K~100 runtime terms (mu pre-sorted), ND = N*D = 2^20, fp32.
//
// R12 = R11 (persistent 444 CTAs, 128 thr, float4 col, double-buffered TMA,
// atomic tile tickets) with:
//  - self-resetting ticket (no reset kernel, single graph node)
//  - terms sorted by (mu,m1); register-cached X1 operand reloaded via
//    predicated LDS only when m1 changes (flag in bit0 of packed offsets).

#define M_CH    9
#define TILE    512                    // floats per channel per tile
#define TILE_B  (TILE * 4)             // 2048 B per channel tile
#define BUF_B   (2 * M_CH * TILE_B)    // 36864 B per buffer
#define THREADS 128
#define NCTAS   444                    // 3 per SM x 148
#define MAXK    112
#define PROGMAX 120

__device__ unsigned int g_ticket = 2u * NCTAS;   // self-resetting

struct Smem {
    float4 buf[2][2 * M_CH * (TILE / 4)];  // 73728 B
    int2   prog[PROGMAX];                  // 960 B  {off1|flag|off2<<16, mult}
    int2   sdat[MAXK];                     // 896 B  sorted {pack, mult}
    int    rawkey[MAXK];                   // 448 B  mu*16+m1 (input order)
    int    skey[MAXK];                     // 448 B  sorted keys
    int    seg[16];
    int    pseg[16];
    unsigned long long mbar[2];
    int    next_tk;
};

__device__ __forceinline__ void mbar_wait(uint32_t addr, int parity)
{
    asm volatile(
        "{\n\t.reg .pred P;\n\t"
        "W_%=:\n\t"
        "mbarrier.try_wait.parity.acquire.cta.shared::cta.b64 P, [%0], %1, 0x989680;\n\t"
        "@P bra.uni D_%=;\n\t"
        "bra.uni W_%=;\n\t"
        "D_%=:\n\t}"
        :: "r"(addr), "r"(parity) : "memory");
}

__device__ __forceinline__ void issue_tile_tma(
    uint32_t dst, const float* X1, const float* X2,
    int tile, int nd4, uint32_t mbar_addr)
{
    asm volatile("mbarrier.arrive.expect_tx.shared.b64 _, [%0], %1;"
                 :: "r"(mbar_addr), "r"((uint32_t)BUF_B) : "memory");
    const char* src1 = (const char*)(X1 + (size_t)tile * TILE);
    const char* src2 = (const char*)(X2 + (size_t)tile * TILE);
    const size_t chanstride = (size_t)nd4 * 16;
#pragma unroll
    for (int m = 0; m < M_CH; m++) {
        asm volatile(
            "cp.async.bulk.shared::cta.global.mbarrier::complete_tx::bytes "
            "[%0], [%1], %2, [%3];"
            :: "r"(dst + m * TILE_B), "l"(src1 + m * chanstride),
               "r"((uint32_t)TILE_B), "r"(mbar_addr) : "memory");
        asm volatile(
            "cp.async.bulk.shared::cta.global.mbarrier::complete_tx::bytes "
            "[%0], [%1], %2, [%3];"
            :: "r"(dst + (M_CH + m) * TILE_B), "l"(src2 + m * chanstride),
               "r"((uint32_t)TILE_B), "r"(mbar_addr) : "memory");
    }
}

__global__ void __launch_bounds__(THREADS, 3)
fused_kernel(const float* __restrict__ X1, const float* __restrict__ X2,
             const int* __restrict__ m1, const int* __restrict__ m2,
             const int* __restrict__ mu, const float* __restrict__ mult,
             float* __restrict__ out, int nd4, int K, int ntiles)
{
    extern __shared__ char smem_raw[];
    Smem* s = (Smem*)smem_raw;
    const int t = threadIdx.x;
    const int bid = blockIdx.x;

    const uint32_t mb0  = (uint32_t)__cvta_generic_to_shared(&s->mbar[0]);
    const uint32_t mb1  = (uint32_t)__cvta_generic_to_shared(&s->mbar[1]);
    const uint32_t buf0 = (uint32_t)__cvta_generic_to_shared(&s->buf[0][0]);
    const uint32_t buf1 = (uint32_t)__cvta_generic_to_shared(&s->buf[1][0]);

    // ---- t0: init mbars, fire both initial TMAs immediately ---------------
    int tile      = bid;                 // buf0
    int tile_next = bid + NCTAS;         // buf1
    if (t == 0) {
        asm volatile("mbarrier.init.shared.b64 [%0], %1;"
                     :: "r"(mb0), "r"(1) : "memory");
        asm volatile("mbarrier.init.shared.b64 [%0], %1;"
                     :: "r"(mb1), "r"(1) : "memory");
        asm volatile("fence.proxy.async.shared::cta;" ::: "memory");
        if (tile < ntiles)
            issue_tile_tma(buf0, X1, X2, tile, nd4, mb0);
        if (tile_next < ntiles)
            issue_tile_tma(buf1, X1, X2, tile_next, nd4, mb1);
    }

    // ---- setup (once per persistent CTA, hidden behind first TMA) ---------
    // phase A: keys in input order
    int myKey = 0, myPack = 0, myMult = 0;
    const bool has_term = (t < K);
    if (has_term) {
        myKey  = mu[t] * 16 + m1[t];
        myPack = (m1[t] * TILE_B) | ((m2[t] * TILE_B) << 16);
        myMult = __float_as_int(mult[t]);
        s->rawkey[t] = myKey;
    }
    __syncthreads();

    // phase B: stable rank sort by (mu,m1); scatter sorted data; mu histogram
    if (has_term) {
        int r = 0;
        for (int j = 0; j < K; j++) {
            int kj = s->rawkey[j];
            r += (kj < myKey) | ((kj == myKey) & (j < t));
        }
        s->skey[r] = myKey;
        s->sdat[r] = make_int2(myPack, myMult);
    }
    if (t <= M_CH) {                   // seg[m] = #{k : mu_k < m}
        int c = 0;
        for (int j = 0; j < K; j++) c += (s->rawkey[j] < t * 16);
        s->seg[t] = c;
    }
    __syncthreads();

    // phase C: warp 0 computes padded segment starts + writes pad entries
    if (t < 16) {
        int segv = (t <= M_CH) ? s->seg[t] : 0;
        const unsigned msk = 0xFFFFu;
        int segn = __shfl_down_sync(msk, segv, 1);
        int len  = segn - segv;          // valid lanes 0..8
        int plen = (len + 1) & ~1;
        int x = plen;
#pragma unroll
        for (int d = 1; d < 16; d <<= 1) {
            int y = __shfl_up_sync(msk, x, d);
            if (t >= d) x += y;
        }
        int psegv = x - plen;            // exclusive scan
        if (t <= 8) {
            s->pseg[t] = psegv;
            if (len & 1)
                s->prog[psegv + len] = make_int2(0, 0);  // pad: no-reload, mult=0
            if (t == 8) s->pseg[9] = psegv + plen;
        }
    }
    __syncthreads();

    // phase D: place sorted terms; reload flag = m1 change vs previous term
    if (has_term) {
        const int key = s->skey[t];
        const int m   = key >> 4;
        const int m1i = key & 15;
        const int reload = (t == 0) || ((s->skey[t - 1] & 15) != m1i);
        const int pos = s->pseg[m] + (t - s->seg[m]);
        int2 d = s->sdat[t];
        s->prog[pos] = make_int2(d.x | reload, d.y);
    }
    __syncthreads();

    // ---- persistent pipelined tile loop ------------------------------------
    float4* __restrict__ out4 = (float4*)out;
    int cur = 0;
    int ph0 = 0, ph1 = 0;
    unsigned long long a0 = 0ull, a1 = 0ull;   // register-cached X1 operand

    while (tile < ntiles) {
        if (t == 0) {                    // grab next ticket early
            unsigned tk = atomicAdd(&g_ticket, 1u);
            if (tk == 2u * NCTAS + (unsigned)ntiles - 1u)
                atomicExch(&g_ticket, 2u * NCTAS);   // last grab: self-reset
            s->next_tk = (int)tk;
        }

        if (cur == 0) { mbar_wait(mb0, ph0); ph0 ^= 1; }
        else          { mbar_wait(mb1, ph1); ph1 ^= 1; }

        const uint32_t colb  = (cur ? buf1 : buf0) + t * 16;
        const uint32_t colb2 = colb + M_CH * TILE_B;
        const int tbase4 = tile * (TILE / 4);
        int kptr = 0;

#pragma unroll
        for (int m = 0; m < M_CH; m++) {
            unsigned long long aL0 = 0ull, aH0 = 0ull;
            unsigned long long aL1 = 0ull, aH1 = 0ull;
            const int k1 = s->pseg[m + 1];
            int k = kptr;
            int4 pr = *(const int4*)&s->prog[k];
            for (; k < k1; k += 2) {
                const int4 curp = pr;
                pr = *(const int4*)&s->prog[k + 2];       // padded: safe
                {
                    unsigned long long b0, b1, c2;
                    asm("{\n\t.reg .pred p;\n\t.reg .u32 f, ofs;\n\t"
                        "and.b32 f, %2, 1;\n\t"
                        "setp.ne.u32 p, f, 0;\n\t"
                        "and.b32 ofs, %2, 0xFFFE;\n\t"
                        "add.u32 ofs, ofs, %3;\n\t"
                        "@p ld.shared.v2.u64 {%0, %1}, [ofs];\n\t}"
                        : "+l"(a0), "+l"(a1)
                        : "r"(curp.x), "r"(colb));
                    asm("ld.shared.v2.u64 {%0, %1}, [%2];"
                        : "=l"(b0), "=l"(b1) : "r"(colb2 + ((unsigned)curp.x >> 16)));
                    asm("mov.b64 %0, {%1, %1};" : "=l"(c2) : "r"(curp.y));
                    asm("mul.rn.f32x2 %0, %1, %2;" : "=l"(b0) : "l"(c2), "l"(b0));
                    asm("mul.rn.f32x2 %0, %1, %2;" : "=l"(b1) : "l"(c2), "l"(b1));
                    asm("fma.rn.f32x2 %0, %1, %2, %3;"
                        : "=l"(aL0) : "l"(a0), "l"(b0), "l"(aL0));
                    asm("fma.rn.f32x2 %0, %1, %2, %3;"
                        : "=l"(aH0) : "l"(a1), "l"(b1), "l"(aH0));
                }
                {
                    unsigned long long b0, b1, c2;
                    asm("{\n\t.reg .pred p;\n\t.reg .u32 f, ofs;\n\t"
                        "and.b32 f, %2, 1;\n\t"
                        "setp.ne.u32 p, f, 0;\n\t"
                        "and.b32 ofs, %2, 0xFFFE;\n\t"
                        "add.u32 ofs, ofs, %3;\n\t"
                        "@p ld.shared.v2.u64 {%0, %1}, [ofs];\n\t}"
                        : "+l"(a0), "+l"(a1)
                        : "r"(curp.z), "r"(colb));
                    asm("ld.shared.v2.u64 {%0, %1}, [%2];"
                        : "=l"(b0), "=l"(b1) : "r"(colb2 + ((unsigned)curp.z >> 16)));
                    asm("mov.b64 %0, {%1, %1};" : "=l"(c2) : "r"(curp.w));
                    asm("mul.rn.f32x2 %0, %1, %2;" : "=l"(b0) : "l"(c2), "l"(b0));
                    asm("mul.rn.f32x2 %0, %1, %2;" : "=l"(b1) : "l"(c2), "l"(b1));
                    asm("fma.rn.f32x2 %0, %1, %2, %3;"
                        : "=l"(aL1) : "l"(a0), "l"(b0), "l"(aL1));
                    asm("fma.rn.f32x2 %0, %1, %2, %3;"
                        : "=l"(aH1) : "l"(a1), "l"(b1), "l"(aH1));
                }
            }
            kptr = k1;
            ulonglong2 acc;
            asm("add.rn.f32x2 %0, %1, %2;" : "=l"(acc.x) : "l"(aL0), "l"(aL1));
            asm("add.rn.f32x2 %0, %1, %2;" : "=l"(acc.y) : "l"(aH0), "l"(aH1));
            *(ulonglong2*)&out4[(size_t)m * nd4 + tbase4 + t] = acc;
        }

        __syncthreads();                 // buf[cur] free; next_tk visible
        const int tk = s->next_tk;
        if (t == 0 && tk < ntiles)
            issue_tile_tma(cur ? buf1 : buf0, X1, X2, tk, nd4, cur ? mb1 : mb0);

        tile = tile_next;
        tile_next = tk;
        cur ^= 1;
    }
}

extern "C" void kernel_launch(void* const* d_in, const int* in_sizes, int n_in,
                              void* d_out, int out_size)
{
    const float* X1   = (const float*)d_in[0];
    const float* X2   = (const float*)d_in[1];
    const int*   m1   = (const int*)d_in[2];
    const int*   m2   = (const int*)d_in[3];
    const int*   mu   = (const int*)d_in[4];
    const float* mult = (const float*)d_in[5];
    float*       out  = (float*)d_out;

    const int K      = in_sizes[2];
    const int ND     = in_sizes[0] / M_CH;   // N*D
    const int nd4    = ND / 4;
    const int ntiles = ND / TILE;

    const int smem = (int)sizeof(Smem);
    cudaFuncSetAttribute(fused_kernel,
                         cudaFuncAttributeMaxDynamicSharedMemorySize, smem);
    fused_kernel<<<NCTAS, THREADS, smem>>>(X1, X2, m1, m2, mu, mult,
                                           out, nd4, K, ntiles);
}